// round 1
// baseline (speedup 1.0000x reference)
#include <cuda_runtime.h>
#include <cuda_bf16.h>
#include <cstdint>

#define B_SZ 4
#define T_SZ 4096
#define DIM 512
#define E3 1536
#define HIST 128

// ---------------- scratch for qkv (allocation-free rule: __device__ global) ---
__device__ float g_qkv[(size_t)B_SZ * T_SZ * E3];   // ~100.7 MB

// ---------------- QKV GEMM: C[M,N] = A[M,K] * W[N,K]^T + bias[N] -------------
// M = B*T = 16384, N = 1536, K = 512
#define BM 128
#define BN 128
#define BK 8
#define TM 8
#define TN 8

__global__ __launch_bounds__(256) void qkv_gemm(
    const float* __restrict__ A, const float* __restrict__ W,
    const float* __restrict__ bias)
{
    __shared__ float As[BK][BM];
    __shared__ float Bs[BK][BN];

    const int bx = blockIdx.x;   // N tile
    const int by = blockIdx.y;   // M tile
    const int tid = threadIdx.x;

    const int K = DIM;
    const int N = E3;

    // global load mapping: each thread loads one float4 of A and one of B per BK step
    const int ldRow  = tid >> 1;          // 0..127
    const int ldCol4 = (tid & 1) << 2;    // 0 or 4

    const float* Ablk = A + (size_t)by * BM * K;
    const float* Wblk = W + (size_t)bx * BN * K;

    const int tr = tid >> 4;   // 0..15 thread row
    const int tc = tid & 15;   // 0..15 thread col

    float acc[TM][TN];
#pragma unroll
    for (int i = 0; i < TM; i++)
#pragma unroll
        for (int j = 0; j < TN; j++) acc[i][j] = 0.f;

    for (int k0 = 0; k0 < K; k0 += BK) {
        float4 a4 = *(const float4*)(Ablk + (size_t)ldRow * K + k0 + ldCol4);
        As[ldCol4 + 0][ldRow] = a4.x;
        As[ldCol4 + 1][ldRow] = a4.y;
        As[ldCol4 + 2][ldRow] = a4.z;
        As[ldCol4 + 3][ldRow] = a4.w;

        float4 b4 = *(const float4*)(Wblk + (size_t)ldRow * K + k0 + ldCol4);
        Bs[ldCol4 + 0][ldRow] = b4.x;
        Bs[ldCol4 + 1][ldRow] = b4.y;
        Bs[ldCol4 + 2][ldRow] = b4.z;
        Bs[ldCol4 + 3][ldRow] = b4.w;

        __syncthreads();

#pragma unroll
        for (int k = 0; k < BK; k++) {
            float ra[TM], rb[TN];
#pragma unroll
            for (int i = 0; i < TM; i++) ra[i] = As[k][tr * TM + i];
#pragma unroll
            for (int j = 0; j < TN; j++) rb[j] = Bs[k][tc * TN + j];
#pragma unroll
            for (int i = 0; i < TM; i++)
#pragma unroll
                for (int j = 0; j < TN; j++)
                    acc[i][j] = fmaf(ra[i], rb[j], acc[i][j]);
        }
        __syncthreads();
    }

    // epilogue: add bias, write to g_qkv
#pragma unroll
    for (int i = 0; i < TM; i++) {
        const int row = by * BM + tr * TM + i;
        const int colBase = bx * BN + tc * TN;
        float* dst = g_qkv + (size_t)row * N + colBase;
#pragma unroll
        for (int j4 = 0; j4 < TN; j4 += 4) {
            float4 v;
            v.x = acc[i][j4 + 0] + bias[colBase + j4 + 0];
            v.y = acc[i][j4 + 1] + bias[colBase + j4 + 1];
            v.z = acc[i][j4 + 2] + bias[colBase + j4 + 2];
            v.w = acc[i][j4 + 3] + bias[colBase + j4 + 3];
            *(float4*)(dst + j4) = v;
        }
    }
}

// ---------------- Banded attention ------------------------------------------
// grid: (T/QT, B). Block: 256 threads, QT=32 queries.
// Keys in band: [i0-128, i0+31] = 160 keys = 5 chunks of 32.
#define QT 32
#define KC 32
#define NCHUNK 5
#define NKEY (NCHUNK * KC)    // 160
#define PITCH 513             // conflict-free stride for 512-wide rows

#define SMEM_FLOATS (QT * PITCH + KC * PITCH + QT * NKEY)
#define SMEM_BYTES  (SMEM_FLOATS * 4)

__global__ __launch_bounds__(256) void banded_attn(float* __restrict__ out)
{
    extern __shared__ float sm[];
    float* Qs  = sm;                       // QT * PITCH
    float* KVs = Qs + QT * PITCH;          // KC * PITCH
    float* Ps  = KVs + KC * PITCH;         // QT * NKEY

    const int b   = blockIdx.y;
    const int i0  = blockIdx.x * QT;
    const int tid = threadIdx.x;

    const float* base = g_qkv + (size_t)b * T_SZ * E3;
    const int jbase = i0 - HIST;           // may be negative

    // ---- load Q tile (32 x 512) ----
    for (int idx = tid; idx < QT * (DIM / 4); idx += 256) {
        const int r  = idx >> 7;            // /128
        const int c4 = (idx & 127) << 2;
        const float4 v = *(const float4*)(base + (size_t)(i0 + r) * E3 + c4);
        float* dst = &Qs[r * PITCH + c4];
        dst[0] = v.x; dst[1] = v.y; dst[2] = v.z; dst[3] = v.w;
    }
    __syncthreads();

    const int ty2 = tid >> 4;   // 0..15
    const int tx2 = tid & 15;   // 0..15
    const float scale = 0.04419417382415922f;   // 1/sqrt(512)

    // ---- phase 1: scores ----
    for (int c = 0; c < NCHUNK; c++) {
        __syncthreads();  // prior chunk's compute done reading KVs
        // load K chunk (rows j = jbase + c*KC + r), zero-fill j<0
        for (int idx = tid; idx < KC * (DIM / 4); idx += 256) {
            const int r  = idx >> 7;
            const int c4 = (idx & 127) << 2;
            const int j  = jbase + c * KC + r;
            float* dst = &KVs[r * PITCH + c4];
            if (j >= 0) {
                const float4 v = *(const float4*)(base + (size_t)j * E3 + DIM + c4);
                dst[0] = v.x; dst[1] = v.y; dst[2] = v.z; dst[3] = v.w;
            } else {
                dst[0] = 0.f; dst[1] = 0.f; dst[2] = 0.f; dst[3] = 0.f;
            }
        }
        __syncthreads();

        const float* qp0 = &Qs[ty2 * PITCH];
        const float* qp1 = &Qs[(ty2 + 16) * PITCH];
        const float* kp0 = &KVs[tx2 * PITCH];
        const float* kp1 = &KVs[(tx2 + 16) * PITCH];
        float a00 = 0.f, a01 = 0.f, a10 = 0.f, a11 = 0.f;
#pragma unroll 8
        for (int d = 0; d < DIM; d++) {
            const float q0 = qp0[d], q1 = qp1[d];
            const float k0 = kp0[d], k1 = kp1[d];
            a00 = fmaf(q0, k0, a00);
            a01 = fmaf(q0, k1, a01);
            a10 = fmaf(q1, k0, a10);
            a11 = fmaf(q1, k1, a11);
        }

        // mask & store; valid iff 0 <= i-j <= HIST and j >= 0
        // i = i0+q ; j = jbase + c*KC + k ; i-j = HIST + q - c*KC - k
#pragma unroll
        for (int sub = 0; sub < 4; sub++) {
            const int q  = (sub & 2) ? (ty2 + 16) : ty2;
            const int k  = (sub & 1) ? (tx2 + 16) : tx2;
            const float a = (sub == 0) ? a00 : (sub == 1) ? a01 : (sub == 2) ? a10 : a11;
            const int delta = HIST + q - c * KC - k;
            const int j = jbase + c * KC + k;
            const bool valid = (delta >= 0) && (delta <= HIST) && (j >= 0);
            Ps[q * NKEY + c * KC + k] = valid ? a * scale : -1e30f;
        }
    }
    __syncthreads();

    // ---- phase 2: softmax over 160 keys per row (warp per 4 rows) ----
    {
        const int w    = tid >> 5;
        const int lane = tid & 31;
        for (int rr = 0; rr < 4; rr++) {
            const int q = w * 4 + rr;
            float vals[NCHUNK];
            float m = -1e30f;
#pragma unroll
            for (int s = 0; s < NCHUNK; s++) {
                vals[s] = Ps[q * NKEY + lane + 32 * s];
                m = fmaxf(m, vals[s]);
            }
#pragma unroll
            for (int off = 16; off; off >>= 1)
                m = fmaxf(m, __shfl_xor_sync(0xFFFFFFFFu, m, off));
            float ssum = 0.f;
#pragma unroll
            for (int s = 0; s < NCHUNK; s++) {
                vals[s] = __expf(vals[s] - m);
                ssum += vals[s];
            }
#pragma unroll
            for (int off = 16; off; off >>= 1)
                ssum += __shfl_xor_sync(0xFFFFFFFFu, ssum, off);
            const float inv = 1.f / ssum;
#pragma unroll
            for (int s = 0; s < NCHUNK; s++)
                Ps[q * NKEY + lane + 32 * s] = vals[s] * inv;
        }
    }
    __syncthreads();

    // ---- phase 3: PV ----
    float o0[32], o1[32];
#pragma unroll
    for (int r = 0; r < 32; r++) { o0[r] = 0.f; o1[r] = 0.f; }

    for (int c = 0; c < NCHUNK; c++) {
        if (c > 0) __syncthreads();
        // load V chunk
        for (int idx = tid; idx < KC * (DIM / 4); idx += 256) {
            const int r  = idx >> 7;
            const int c4 = (idx & 127) << 2;
            const int j  = jbase + c * KC + r;
            float* dst = &KVs[r * PITCH + c4];
            if (j >= 0) {
                const float4 v = *(const float4*)(base + (size_t)j * E3 + 2 * DIM + c4);
                dst[0] = v.x; dst[1] = v.y; dst[2] = v.z; dst[3] = v.w;
            } else {
                dst[0] = 0.f; dst[1] = 0.f; dst[2] = 0.f; dst[3] = 0.f;
            }
        }
        __syncthreads();

        const float* pr0 = &Ps[ty2 * NKEY + c * KC];
        const float* pr1 = &Ps[(ty2 + 16) * NKEY + c * KC];
#pragma unroll 4
        for (int jj = 0; jj < KC; jj++) {
            const float p0 = pr0[jj];
            const float p1 = pr1[jj];
            const float* vp = &KVs[jj * PITCH + tx2];
#pragma unroll
            for (int r = 0; r < 32; r++) {
                const float v = vp[r * 16];
                o0[r] = fmaf(p0, v, o0[r]);
                o1[r] = fmaf(p1, v, o1[r]);
            }
        }
    }

    // ---- store output (B, T, DIM) ----
    float* orow0 = out + ((size_t)b * T_SZ + (i0 + ty2)) * DIM + tx2;
    float* orow1 = out + ((size_t)b * T_SZ + (i0 + ty2 + 16)) * DIM + tx2;
#pragma unroll
    for (int r = 0; r < 32; r++) {
        orow0[r * 16] = o0[r];
        orow1[r * 16] = o1[r];
    }
}

// ---------------- launch -----------------------------------------------------
extern "C" void kernel_launch(void* const* d_in, const int* in_sizes, int n_in,
                              void* d_out, int out_size)
{
    const float* x    = (const float*)d_in[0];   // (4,4096,512)
    const float* Wqkv = (const float*)d_in[1];   // (1536,512)
    const float* bqkv = (const float*)d_in[2];   // (1536,)
    float* out = (float*)d_out;                  // (4,4096,512)

    cudaFuncSetAttribute(banded_attn,
                         cudaFuncAttributeMaxDynamicSharedMemorySize, SMEM_BYTES);

    // QKV projection: M=16384 rows, N=1536 cols
    dim3 ggrid(E3 / BN, (B_SZ * T_SZ) / BM);   // (12, 128)
    qkv_gemm<<<ggrid, 256>>>(x, Wqkv, bqkv);

    // Banded attention
    dim3 agrid(T_SZ / QT, B_SZ);               // (128, 4)
    banded_attn<<<agrid, 256, SMEM_BYTES>>>(out);
}

// round 2
// speedup vs baseline: 1.4879x; 1.4879x over previous
#include <cuda_runtime.h>
#include <cuda_bf16.h>
#include <cstdint>

#define B_SZ 4
#define T_SZ 4096
#define DIM 512
#define E3 1536
#define HIST 128
#define M_TOT (B_SZ * T_SZ)   // 16384

// ---------------- device scratch (allocation-free rule) ----------------------
__device__ __align__(16) float g_qkv[(size_t)B_SZ * T_SZ * E3];        // ~100.7 MB
__device__ __align__(16) __nv_bfloat16 g_Ah[(size_t)M_TOT * DIM];      // 16.8 MB
__device__ __align__(16) __nv_bfloat16 g_Al[(size_t)M_TOT * DIM];
__device__ __align__(16) __nv_bfloat16 g_Wh[(size_t)E3 * DIM];         // 1.6 MB
__device__ __align__(16) __nv_bfloat16 g_Wl[(size_t)E3 * DIM];

// ---------------- fp32 -> (hi, lo) bf16 split --------------------------------
__global__ __launch_bounds__(256) void cvt_split(
    const float* __restrict__ src,
    __nv_bfloat16* __restrict__ hi, __nv_bfloat16* __restrict__ lo, int n4)
{
    int i = blockIdx.x * 256 + threadIdx.x;
    if (i >= n4) return;
    float4 v = ((const float4*)src)[i];
    float vv[4] = {v.x, v.y, v.z, v.w};
    ushort4 h, l;
    unsigned short hs[4], ls[4];
#pragma unroll
    for (int j = 0; j < 4; j++) {
        __nv_bfloat16 hb = __float2bfloat16(vv[j]);
        __nv_bfloat16 lb = __float2bfloat16(vv[j] - __bfloat162float(hb));
        hs[j] = __bfloat16_as_ushort(hb);
        ls[j] = __bfloat16_as_ushort(lb);
    }
    h.x = hs[0]; h.y = hs[1]; h.z = hs[2]; h.w = hs[3];
    l.x = ls[0]; l.y = ls[1]; l.z = ls[2]; l.w = ls[3];
    ((ushort4*)hi)[i] = h;
    ((ushort4*)lo)[i] = l;
}

// ---------------- QKV GEMM via bf16x3 mma.sync -------------------------------
// C[M,N] = A[M,K] * W[N,K]^T + bias ; M=16384 N=1536 K=512 (x3 passes)
#define GBM 128
#define GBN 128
#define GBK 32
#define APITCH 40    // bf16 units; conflict-free for fragment loads

__global__ __launch_bounds__(256) void qkv_mma(const float* __restrict__ bias)
{
    __shared__ __align__(16) __nv_bfloat16 As[GBM][APITCH];
    __shared__ __align__(16) __nv_bfloat16 Bs[GBN][APITCH];

    const int tid  = threadIdx.x;
    const int warp = tid >> 5, lane = tid & 31;
    const int wm = (warp >> 1) * 32;   // 4 warps along M
    const int wn = (warp & 1) * 64;    // 2 warps along N
    const int g  = lane >> 2, tig = lane & 3;

    const int bm = blockIdx.y * GBM;
    const int bn = blockIdx.x * GBN;

    float acc[2][8][4] = {};

    const __nv_bfloat16* APASS[3] = {g_Ah, g_Ah, g_Al};
    const __nv_bfloat16* BPASS[3] = {g_Wh, g_Wl, g_Wh};

    for (int p = 0; p < 3; p++) {
        const __nv_bfloat16* Ag = APASS[p] + (size_t)bm * DIM;
        const __nv_bfloat16* Bg = BPASS[p] + (size_t)bn * DIM;

        for (int k0 = 0; k0 < DIM; k0 += GBK) {
            __syncthreads();
#pragma unroll
            for (int it = 0; it < 2; it++) {
                const int idx = tid + it * 256;       // 0..511
                const int r = idx >> 2;               // 0..127
                const int c = (idx & 3) * 8;          // 0,8,16,24
                *(uint4*)&As[r][c] = *(const uint4*)(Ag + (size_t)r * DIM + k0 + c);
                *(uint4*)&Bs[r][c] = *(const uint4*)(Bg + (size_t)r * DIM + k0 + c);
            }
            __syncthreads();

#pragma unroll
            for (int ks = 0; ks < 2; ks++) {
                const int k = ks * 16;
                uint32_t a[2][4];
#pragma unroll
                for (int mi = 0; mi < 2; mi++) {
                    const int r0 = wm + mi * 16 + g;
                    a[mi][0] = *(const uint32_t*)&As[r0    ][k     + tig * 2];
                    a[mi][1] = *(const uint32_t*)&As[r0 + 8][k     + tig * 2];
                    a[mi][2] = *(const uint32_t*)&As[r0    ][k + 8 + tig * 2];
                    a[mi][3] = *(const uint32_t*)&As[r0 + 8][k + 8 + tig * 2];
                }
#pragma unroll
                for (int ni = 0; ni < 8; ni++) {
                    const int n0 = wn + ni * 8 + g;
                    const uint32_t b0 = *(const uint32_t*)&Bs[n0][k     + tig * 2];
                    const uint32_t b1 = *(const uint32_t*)&Bs[n0][k + 8 + tig * 2];
#pragma unroll
                    for (int mi = 0; mi < 2; mi++) {
                        asm volatile(
                            "mma.sync.aligned.m16n8k16.row.col.f32.bf16.bf16.f32 "
                            "{%0,%1,%2,%3}, {%4,%5,%6,%7}, {%8,%9}, {%0,%1,%2,%3};\n"
                            : "+f"(acc[mi][ni][0]), "+f"(acc[mi][ni][1]),
                              "+f"(acc[mi][ni][2]), "+f"(acc[mi][ni][3])
                            : "r"(a[mi][0]), "r"(a[mi][1]), "r"(a[mi][2]), "r"(a[mi][3]),
                              "r"(b0), "r"(b1));
                    }
                }
            }
        }
    }

    // epilogue: bias + store fp32
#pragma unroll
    for (int mi = 0; mi < 2; mi++) {
#pragma unroll
        for (int ni = 0; ni < 8; ni++) {
            const int r0 = bm + wm + mi * 16 + g;
            const int cc = bn + wn + ni * 8 + tig * 2;
            const float bb0 = bias[cc], bb1 = bias[cc + 1];
            float2 v0 = {acc[mi][ni][0] + bb0, acc[mi][ni][1] + bb1};
            float2 v1 = {acc[mi][ni][2] + bb0, acc[mi][ni][3] + bb1};
            *(float2*)&g_qkv[(size_t)r0 * E3 + cc]       = v0;
            *(float2*)&g_qkv[(size_t)(r0 + 8) * E3 + cc] = v1;
        }
    }
}

// ---------------- Banded attention (unchanged from R1) -----------------------
#define QT 32
#define KC 32
#define NCHUNK 5
#define NKEY (NCHUNK * KC)
#define PITCH 513

#define SMEM_FLOATS (QT * PITCH + KC * PITCH + QT * NKEY)
#define SMEM_BYTES  (SMEM_FLOATS * 4)

__global__ __launch_bounds__(256) void banded_attn(float* __restrict__ out)
{
    extern __shared__ float sm[];
    float* Qs  = sm;
    float* KVs = Qs + QT * PITCH;
    float* Ps  = KVs + KC * PITCH;

    const int b   = blockIdx.y;
    const int i0  = blockIdx.x * QT;
    const int tid = threadIdx.x;

    const float* base = g_qkv + (size_t)b * T_SZ * E3;
    const int jbase = i0 - HIST;

    for (int idx = tid; idx < QT * (DIM / 4); idx += 256) {
        const int r  = idx >> 7;
        const int c4 = (idx & 127) << 2;
        const float4 v = *(const float4*)(base + (size_t)(i0 + r) * E3 + c4);
        float* dst = &Qs[r * PITCH + c4];
        dst[0] = v.x; dst[1] = v.y; dst[2] = v.z; dst[3] = v.w;
    }
    __syncthreads();

    const int ty2 = tid >> 4;
    const int tx2 = tid & 15;
    const float scale = 0.04419417382415922f;

    for (int c = 0; c < NCHUNK; c++) {
        __syncthreads();
        for (int idx = tid; idx < KC * (DIM / 4); idx += 256) {
            const int r  = idx >> 7;
            const int c4 = (idx & 127) << 2;
            const int j  = jbase + c * KC + r;
            float* dst = &KVs[r * PITCH + c4];
            if (j >= 0) {
                const float4 v = *(const float4*)(base + (size_t)j * E3 + DIM + c4);
                dst[0] = v.x; dst[1] = v.y; dst[2] = v.z; dst[3] = v.w;
            } else {
                dst[0] = 0.f; dst[1] = 0.f; dst[2] = 0.f; dst[3] = 0.f;
            }
        }
        __syncthreads();

        const float* qp0 = &Qs[ty2 * PITCH];
        const float* qp1 = &Qs[(ty2 + 16) * PITCH];
        const float* kp0 = &KVs[tx2 * PITCH];
        const float* kp1 = &KVs[(tx2 + 16) * PITCH];
        float a00 = 0.f, a01 = 0.f, a10 = 0.f, a11 = 0.f;
#pragma unroll 8
        for (int d = 0; d < DIM; d++) {
            const float q0 = qp0[d], q1 = qp1[d];
            const float k0 = kp0[d], k1 = kp1[d];
            a00 = fmaf(q0, k0, a00);
            a01 = fmaf(q0, k1, a01);
            a10 = fmaf(q1, k0, a10);
            a11 = fmaf(q1, k1, a11);
        }

#pragma unroll
        for (int sub = 0; sub < 4; sub++) {
            const int q  = (sub & 2) ? (ty2 + 16) : ty2;
            const int k  = (sub & 1) ? (tx2 + 16) : tx2;
            const float a = (sub == 0) ? a00 : (sub == 1) ? a01 : (sub == 2) ? a10 : a11;
            const int delta = HIST + q - c * KC - k;
            const int j = jbase + c * KC + k;
            const bool valid = (delta >= 0) && (delta <= HIST) && (j >= 0);
            Ps[q * NKEY + c * KC + k] = valid ? a * scale : -1e30f;
        }
    }
    __syncthreads();

    {
        const int w    = tid >> 5;
        const int lane = tid & 31;
        for (int rr = 0; rr < 4; rr++) {
            const int q = w * 4 + rr;
            float vals[NCHUNK];
            float m = -1e30f;
#pragma unroll
            for (int s = 0; s < NCHUNK; s++) {
                vals[s] = Ps[q * NKEY + lane + 32 * s];
                m = fmaxf(m, vals[s]);
            }
#pragma unroll
            for (int off = 16; off; off >>= 1)
                m = fmaxf(m, __shfl_xor_sync(0xFFFFFFFFu, m, off));
            float ssum = 0.f;
#pragma unroll
            for (int s = 0; s < NCHUNK; s++) {
                vals[s] = __expf(vals[s] - m);
                ssum += vals[s];
            }
#pragma unroll
            for (int off = 16; off; off >>= 1)
                ssum += __shfl_xor_sync(0xFFFFFFFFu, ssum, off);
            const float inv = 1.f / ssum;
#pragma unroll
            for (int s = 0; s < NCHUNK; s++)
                Ps[q * NKEY + lane + 32 * s] = vals[s] * inv;
        }
    }
    __syncthreads();

    float o0[32], o1[32];
#pragma unroll
    for (int r = 0; r < 32; r++) { o0[r] = 0.f; o1[r] = 0.f; }

    for (int c = 0; c < NCHUNK; c++) {
        if (c > 0) __syncthreads();
        for (int idx = tid; idx < KC * (DIM / 4); idx += 256) {
            const int r  = idx >> 7;
            const int c4 = (idx & 127) << 2;
            const int j  = jbase + c * KC + r;
            float* dst = &KVs[r * PITCH + c4];
            if (j >= 0) {
                const float4 v = *(const float4*)(base + (size_t)j * E3 + 2 * DIM + c4);
                dst[0] = v.x; dst[1] = v.y; dst[2] = v.z; dst[3] = v.w;
            } else {
                dst[0] = 0.f; dst[1] = 0.f; dst[2] = 0.f; dst[3] = 0.f;
            }
        }
        __syncthreads();

        const float* pr0 = &Ps[ty2 * NKEY + c * KC];
        const float* pr1 = &Ps[(ty2 + 16) * NKEY + c * KC];
#pragma unroll 4
        for (int jj = 0; jj < KC; jj++) {
            const float p0 = pr0[jj];
            const float p1 = pr1[jj];
            const float* vp = &KVs[jj * PITCH + tx2];
#pragma unroll
            for (int r = 0; r < 32; r++) {
                const float v = vp[r * 16];
                o0[r] = fmaf(p0, v, o0[r]);
                o1[r] = fmaf(p1, v, o1[r]);
            }
        }
    }

    float* orow0 = out + ((size_t)b * T_SZ + (i0 + ty2)) * DIM + tx2;
    float* orow1 = out + ((size_t)b * T_SZ + (i0 + ty2 + 16)) * DIM + tx2;
#pragma unroll
    for (int r = 0; r < 32; r++) {
        orow0[r * 16] = o0[r];
        orow1[r * 16] = o1[r];
    }
}

// ---------------- launch -----------------------------------------------------
extern "C" void kernel_launch(void* const* d_in, const int* in_sizes, int n_in,
                              void* d_out, int out_size)
{
    const float* x    = (const float*)d_in[0];   // (4,4096,512)
    const float* Wqkv = (const float*)d_in[1];   // (1536,512)
    const float* bqkv = (const float*)d_in[2];   // (1536,)
    float* out = (float*)d_out;                  // (4,4096,512)

    cudaFuncSetAttribute(banded_attn,
                         cudaFuncAttributeMaxDynamicSharedMemorySize, SMEM_BYTES);

    // resolve device-global scratch addresses for the convert kernels
    __nv_bfloat16 *ah, *al, *wh, *wl;
    cudaGetSymbolAddress((void**)&ah, g_Ah);
    cudaGetSymbolAddress((void**)&al, g_Al);
    cudaGetSymbolAddress((void**)&wh, g_Wh);
    cudaGetSymbolAddress((void**)&wl, g_Wl);

    // split x and W into bf16 hi/lo
    {
        int n4 = (M_TOT * DIM) / 4;                    // 2097152
        cvt_split<<<(n4 + 255) / 256, 256>>>(x, ah, al, n4);
    }
    {
        int n4 = (E3 * DIM) / 4;                       // 196608
        cvt_split<<<(n4 + 255) / 256, 256>>>(Wqkv, wh, wl, n4);
    }

    // QKV projection via tensor cores
    dim3 ggrid(E3 / GBN, M_TOT / GBM);                 // (12, 128)
    qkv_mma<<<ggrid, 256>>>(bqkv);

    // Banded attention
    dim3 agrid(T_SZ / QT, B_SZ);                       // (128, 4)
    banded_attn<<<agrid, 256, SMEM_BYTES>>>(out);
}

// round 3
// speedup vs baseline: 2.3943x; 1.6092x over previous
#include <cuda_runtime.h>
#include <cuda_bf16.h>
#include <cstdint>

#define B_SZ 4
#define T_SZ 4096
#define DIM 512
#define E3 1536
#define HIST 128
#define M_TOT (B_SZ * T_SZ)   // 16384
#define QSCALE 0.04419417382415922f   // 1/sqrt(512)

// ---------------- device scratch (allocation-free rule) ----------------------
__device__ __align__(16) __nv_bfloat16 g_Ah[(size_t)M_TOT * DIM];
__device__ __align__(16) __nv_bfloat16 g_Al[(size_t)M_TOT * DIM];
__device__ __align__(16) __nv_bfloat16 g_Wh[(size_t)E3 * DIM];
__device__ __align__(16) __nv_bfloat16 g_Wl[(size_t)E3 * DIM];

// qkv outputs, split bf16. q has softmax scale folded in. v stored transposed (b, d, t).
__device__ __align__(16) __nv_bfloat16 g_qh[(size_t)M_TOT * DIM];
__device__ __align__(16) __nv_bfloat16 g_ql[(size_t)M_TOT * DIM];
__device__ __align__(16) __nv_bfloat16 g_kh[(size_t)M_TOT * DIM];
__device__ __align__(16) __nv_bfloat16 g_kl[(size_t)M_TOT * DIM];
__device__ __align__(16) __nv_bfloat16 g_vth[(size_t)B_SZ * DIM * T_SZ];
__device__ __align__(16) __nv_bfloat16 g_vtl[(size_t)B_SZ * DIM * T_SZ];

// ---------------- helpers ----------------------------------------------------
__device__ __forceinline__ void split2(float v0, float v1, uint32_t& h, uint32_t& l)
{
    __nv_bfloat16 h0 = __float2bfloat16(v0);
    __nv_bfloat16 h1 = __float2bfloat16(v1);
    __nv_bfloat16 l0 = __float2bfloat16(v0 - __bfloat162float(h0));
    __nv_bfloat16 l1 = __float2bfloat16(v1 - __bfloat162float(h1));
    h = ((uint32_t)__bfloat16_as_ushort(h1) << 16) | __bfloat16_as_ushort(h0);
    l = ((uint32_t)__bfloat16_as_ushort(l1) << 16) | __bfloat16_as_ushort(l0);
}

__device__ __forceinline__ void mma16816(float* c, const uint32_t* a, uint32_t b0, uint32_t b1)
{
    asm volatile(
        "mma.sync.aligned.m16n8k16.row.col.f32.bf16.bf16.f32 "
        "{%0,%1,%2,%3}, {%4,%5,%6,%7}, {%8,%9}, {%0,%1,%2,%3};\n"
        : "+f"(c[0]), "+f"(c[1]), "+f"(c[2]), "+f"(c[3])
        : "r"(a[0]), "r"(a[1]), "r"(a[2]), "r"(a[3]), "r"(b0), "r"(b1));
}

// ---------------- fp32 -> (hi, lo) bf16 split --------------------------------
__global__ __launch_bounds__(256) void cvt_split(
    const float* __restrict__ src,
    __nv_bfloat16* __restrict__ hi, __nv_bfloat16* __restrict__ lo, int n4)
{
    int i = blockIdx.x * 256 + threadIdx.x;
    if (i >= n4) return;
    float4 v = ((const float4*)src)[i];
    uint32_t h0, l0, h1, l1;
    split2(v.x, v.y, h0, l0);
    split2(v.z, v.w, h1, l1);
    uint2 h = {h0, h1}, l = {l0, l1};
    ((uint2*)hi)[i] = h;
    ((uint2*)lo)[i] = l;
}

// ---------------- QKV GEMM via bf16x3 mma.sync -------------------------------
#define GBM 128
#define GBN 128
#define GBK 32
#define APITCH 40

__global__ __launch_bounds__(256) void qkv_mma(const float* __restrict__ bias)
{
    __shared__ __align__(16) __nv_bfloat16 As[GBM][APITCH];
    __shared__ __align__(16) __nv_bfloat16 Bs[GBN][APITCH];

    const int tid  = threadIdx.x;
    const int warp = tid >> 5, lane = tid & 31;
    const int wm = (warp >> 1) * 32;
    const int wn = (warp & 1) * 64;
    const int g  = lane >> 2, tig = lane & 3;

    const int bm = blockIdx.y * GBM;
    const int bn = blockIdx.x * GBN;

    float acc[2][8][4] = {};

    const __nv_bfloat16* APASS[3] = {g_Ah, g_Ah, g_Al};
    const __nv_bfloat16* BPASS[3] = {g_Wh, g_Wl, g_Wh};

    for (int p = 0; p < 3; p++) {
        const __nv_bfloat16* Ag = APASS[p] + (size_t)bm * DIM;
        const __nv_bfloat16* Bg = BPASS[p] + (size_t)bn * DIM;

        for (int k0 = 0; k0 < DIM; k0 += GBK) {
            __syncthreads();
#pragma unroll
            for (int it = 0; it < 2; it++) {
                const int idx = tid + it * 256;
                const int r = idx >> 2;
                const int c = (idx & 3) * 8;
                *(uint4*)&As[r][c] = *(const uint4*)(Ag + (size_t)r * DIM + k0 + c);
                *(uint4*)&Bs[r][c] = *(const uint4*)(Bg + (size_t)r * DIM + k0 + c);
            }
            __syncthreads();

#pragma unroll
            for (int ks = 0; ks < 2; ks++) {
                const int k = ks * 16;
                uint32_t a[2][4];
#pragma unroll
                for (int mi = 0; mi < 2; mi++) {
                    const int r0 = wm + mi * 16 + g;
                    a[mi][0] = *(const uint32_t*)&As[r0    ][k     + tig * 2];
                    a[mi][1] = *(const uint32_t*)&As[r0 + 8][k     + tig * 2];
                    a[mi][2] = *(const uint32_t*)&As[r0    ][k + 8 + tig * 2];
                    a[mi][3] = *(const uint32_t*)&As[r0 + 8][k + 8 + tig * 2];
                }
#pragma unroll
                for (int ni = 0; ni < 8; ni++) {
                    const int n0 = wn + ni * 8 + g;
                    const uint32_t b0 = *(const uint32_t*)&Bs[n0][k     + tig * 2];
                    const uint32_t b1 = *(const uint32_t*)&Bs[n0][k + 8 + tig * 2];
#pragma unroll
                    for (int mi = 0; mi < 2; mi++)
                        mma16816(acc[mi][ni], a[mi], b0, b1);
                }
            }
        }
    }

    // epilogue: bias, then route to q (scaled) / k / v-transposed split-bf16 stores
    const int sec = bn >> 9;            // 0=q, 1=k, 2=v (block fits in one section)
#pragma unroll
    for (int mi = 0; mi < 2; mi++) {
#pragma unroll
        for (int ni = 0; ni < 8; ni++) {
            const int m0 = bm + wm + mi * 16 + g;
            const int cc = bn + wn + ni * 8 + tig * 2;
            const int lc = cc & 511;
            const float bb0 = bias[cc], bb1 = bias[cc + 1];
            float v00 = acc[mi][ni][0] + bb0, v01 = acc[mi][ni][1] + bb1;
            float v10 = acc[mi][ni][2] + bb0, v11 = acc[mi][ni][3] + bb1;
            if (sec == 0) { v00 *= QSCALE; v01 *= QSCALE; v10 *= QSCALE; v11 *= QSCALE; }
            uint32_t h0, l0, h1, l1;
            split2(v00, v01, h0, l0);
            split2(v10, v11, h1, l1);
            if (sec == 0) {
                *(uint32_t*)&g_qh[(size_t)m0 * DIM + lc]       = h0;
                *(uint32_t*)&g_ql[(size_t)m0 * DIM + lc]       = l0;
                *(uint32_t*)&g_qh[(size_t)(m0 + 8) * DIM + lc] = h1;
                *(uint32_t*)&g_ql[(size_t)(m0 + 8) * DIM + lc] = l1;
            } else if (sec == 1) {
                *(uint32_t*)&g_kh[(size_t)m0 * DIM + lc]       = h0;
                *(uint32_t*)&g_kl[(size_t)m0 * DIM + lc]       = l0;
                *(uint32_t*)&g_kh[(size_t)(m0 + 8) * DIM + lc] = h1;
                *(uint32_t*)&g_kl[(size_t)(m0 + 8) * DIM + lc] = l1;
            } else {
                const int b = m0 >> 12, t = m0 & 4095;
                const size_t base = (size_t)b * DIM * T_SZ;
                g_vth[base + (size_t)lc * T_SZ + t]           = __ushort_as_bfloat16((unsigned short)(h0 & 0xFFFF));
                g_vth[base + (size_t)(lc + 1) * T_SZ + t]     = __ushort_as_bfloat16((unsigned short)(h0 >> 16));
                g_vtl[base + (size_t)lc * T_SZ + t]           = __ushort_as_bfloat16((unsigned short)(l0 & 0xFFFF));
                g_vtl[base + (size_t)(lc + 1) * T_SZ + t]     = __ushort_as_bfloat16((unsigned short)(l0 >> 16));
                g_vth[base + (size_t)lc * T_SZ + t + 8]       = __ushort_as_bfloat16((unsigned short)(h1 & 0xFFFF));
                g_vth[base + (size_t)(lc + 1) * T_SZ + t + 8] = __ushort_as_bfloat16((unsigned short)(h1 >> 16));
                g_vtl[base + (size_t)lc * T_SZ + t + 8]       = __ushort_as_bfloat16((unsigned short)(l1 & 0xFFFF));
                g_vtl[base + (size_t)(lc + 1) * T_SZ + t + 8] = __ushort_as_bfloat16((unsigned short)(l1 >> 16));
            }
        }
    }
}

// ---------------- Banded attention via mma.sync ------------------------------
// 64 queries x 192 band keys per block, 8 warps.
#define QT 64
#define NK 192
#define DC 64
#define KP 72      // bf16 pitch for Q/K chunk
#define PP 200     // pitch for Ps (f32) and Ph/Pl/Vt (bf16)

// smem layout (bytes):
//  region A (union):
//    phase A: Qh@0 (9216), Ql@9216, Kh@18432 (27648), Kl@46080   -> 73728
//    phase B: Ps f32 @0 (64*200*4 = 51200)
//    phase C: Vth@0 (25600), Vtl@25600
//  region B: Ph@73728 (25600), Pl@99328 (25600)
#define AT_SMEM 124928

__global__ __launch_bounds__(256) void attn_mma(float* __restrict__ out)
{
    extern __shared__ char sm[];
    __nv_bfloat16* Qh = (__nv_bfloat16*)sm;
    __nv_bfloat16* Ql = (__nv_bfloat16*)(sm + 9216);
    __nv_bfloat16* Kh = (__nv_bfloat16*)(sm + 18432);
    __nv_bfloat16* Kl = (__nv_bfloat16*)(sm + 46080);
    float*         Ps = (float*)sm;
    __nv_bfloat16* Vth = (__nv_bfloat16*)sm;
    __nv_bfloat16* Vtl = (__nv_bfloat16*)(sm + 25600);
    __nv_bfloat16* Ph = (__nv_bfloat16*)(sm + 73728);
    __nv_bfloat16* Pl = (__nv_bfloat16*)(sm + 99328);

    const int b   = blockIdx.y;
    const int i0  = blockIdx.x * QT;
    const int tid = threadIdx.x;
    const int warp = tid >> 5, lane = tid & 31;
    const int g = lane >> 2, tig = lane & 3;
    const int jbase = i0 - HIST;

    // ---------------- phase A: S = Q K^T (3-product split) -------------------
    const int wm = (warp >> 2) * 32;       // 2 warp-groups along M
    const int wn = (warp & 3) * 48;        // 4 warp-groups along N
    float acc[2][6][4] = {};

    for (int dc = 0; dc < DIM / DC; dc++) {
        const int d0 = dc * DC;
        __syncthreads();
#pragma unroll
        for (int it = 0; it < 2; it++) {
            const int idx = tid + it * 256;
            const int r = idx >> 3, c8 = (idx & 7) * 8;
            const size_t off = (size_t)(b * T_SZ + i0 + r) * DIM + d0 + c8;
            *(uint4*)&Qh[r * KP + c8] = *(const uint4*)(g_qh + off);
            *(uint4*)&Ql[r * KP + c8] = *(const uint4*)(g_ql + off);
        }
#pragma unroll
        for (int it = 0; it < 6; it++) {
            const int idx = tid + it * 256;
            const int r = idx >> 3, c8 = (idx & 7) * 8;
            const int j = jbase + r;
            const int jc = j < 0 ? 0 : j;   // clamped; masked later
            const size_t off = (size_t)(b * T_SZ + jc) * DIM + d0 + c8;
            *(uint4*)&Kh[r * KP + c8] = *(const uint4*)(g_kh + off);
            *(uint4*)&Kl[r * KP + c8] = *(const uint4*)(g_kl + off);
        }
        __syncthreads();

#pragma unroll
        for (int ks = 0; ks < DC / 16; ks++) {
            const int k = ks * 16;
            uint32_t ah[2][4], al[2][4];
#pragma unroll
            for (int mi = 0; mi < 2; mi++) {
                const int r0 = wm + mi * 16 + g;
                ah[mi][0] = *(const uint32_t*)&Qh[r0 * KP + k + tig * 2];
                ah[mi][1] = *(const uint32_t*)&Qh[(r0 + 8) * KP + k + tig * 2];
                ah[mi][2] = *(const uint32_t*)&Qh[r0 * KP + k + 8 + tig * 2];
                ah[mi][3] = *(const uint32_t*)&Qh[(r0 + 8) * KP + k + 8 + tig * 2];
                al[mi][0] = *(const uint32_t*)&Ql[r0 * KP + k + tig * 2];
                al[mi][1] = *(const uint32_t*)&Ql[(r0 + 8) * KP + k + tig * 2];
                al[mi][2] = *(const uint32_t*)&Ql[r0 * KP + k + 8 + tig * 2];
                al[mi][3] = *(const uint32_t*)&Ql[(r0 + 8) * KP + k + 8 + tig * 2];
            }
#pragma unroll
            for (int ni = 0; ni < 6; ni++) {
                const int n0 = wn + ni * 8 + g;
                const uint32_t bh0 = *(const uint32_t*)&Kh[n0 * KP + k + tig * 2];
                const uint32_t bh1 = *(const uint32_t*)&Kh[n0 * KP + k + 8 + tig * 2];
                const uint32_t bl0 = *(const uint32_t*)&Kl[n0 * KP + k + tig * 2];
                const uint32_t bl1 = *(const uint32_t*)&Kl[n0 * KP + k + 8 + tig * 2];
#pragma unroll
                for (int mi = 0; mi < 2; mi++) {
                    mma16816(acc[mi][ni], ah[mi], bh0, bh1);
                    mma16816(acc[mi][ni], ah[mi], bl0, bl1);
                    mma16816(acc[mi][ni], al[mi], bh0, bh1);
                }
            }
        }
    }
    __syncthreads();

    // masked store of S to Ps
#pragma unroll
    for (int mi = 0; mi < 2; mi++) {
#pragma unroll
        for (int ni = 0; ni < 6; ni++) {
            const int m0 = wm + mi * 16 + g;
            const int n0 = wn + ni * 8 + tig * 2;
#pragma unroll
            for (int e = 0; e < 4; e++) {
                const int m = m0 + (e >> 1) * 8;
                const int n = n0 + (e & 1);
                const bool valid = (n >= m) && (n <= m + HIST) && (i0 + n >= HIST);
                Ps[m * PP + n] = valid ? acc[mi][ni][e] : -1e30f;
            }
        }
    }
    __syncthreads();

    // ---------------- phase B: softmax + split P to bf16 hi/lo ---------------
#pragma unroll
    for (int rr = 0; rr < 8; rr++) {
        const int q = warp * 8 + rr;
        float v[6];
        float mx = -1e30f;
#pragma unroll
        for (int s = 0; s < 6; s++) {
            v[s] = Ps[q * PP + lane + 32 * s];
            mx = fmaxf(mx, v[s]);
        }
#pragma unroll
        for (int off = 16; off; off >>= 1)
            mx = fmaxf(mx, __shfl_xor_sync(0xFFFFFFFFu, mx, off));
        float sum = 0.f;
#pragma unroll
        for (int s = 0; s < 6; s++) {
            v[s] = __expf(v[s] - mx);
            sum += v[s];
        }
#pragma unroll
        for (int off = 16; off; off >>= 1)
            sum += __shfl_xor_sync(0xFFFFFFFFu, sum, off);
        const float inv = 1.f / sum;
#pragma unroll
        for (int s = 0; s < 6; s++) {
            const float p = v[s] * inv;
            const __nv_bfloat16 ph = __float2bfloat16(p);
            const __nv_bfloat16 pl = __float2bfloat16(p - __bfloat162float(ph));
            Ph[q * PP + lane + 32 * s] = ph;
            Pl[q * PP + lane + 32 * s] = pl;
        }
    }

    // ---------------- phase C: O = P V (3-product split) ---------------------
    const int wn2 = (warp & 3) * 16;       // 4 warp-groups along D
    const size_t vbase = (size_t)b * DIM * T_SZ;

    for (int dc = 0; dc < DIM / DC; dc++) {
        const int d0 = dc * DC;
        __syncthreads();   // Ps dead / previous Vt consumed
#pragma unroll
        for (int it = 0; it < 12; it++) {
            const int idx = tid + it * 256;
            const int r = idx / 48;
            const int c = (idx % 48) * 4;
            int j = jbase + c;
            if (j < 0) j = 0;              // clamped; p=0 there
            const size_t off = vbase + (size_t)(d0 + r) * T_SZ + j;
            *(uint2*)&Vth[r * PP + c] = *(const uint2*)(g_vth + off);
            *(uint2*)&Vtl[r * PP + c] = *(const uint2*)(g_vtl + off);
        }
        __syncthreads();

        float oacc[2][2][4] = {};
#pragma unroll
        for (int ks = 0; ks < NK / 16; ks++) {
            const int k = ks * 16;
            uint32_t ph_[2][4], pl_[2][4];
#pragma unroll
            for (int mi = 0; mi < 2; mi++) {
                const int r0 = wm + mi * 16 + g;
                ph_[mi][0] = *(const uint32_t*)&Ph[r0 * PP + k + tig * 2];
                ph_[mi][1] = *(const uint32_t*)&Ph[(r0 + 8) * PP + k + tig * 2];
                ph_[mi][2] = *(const uint32_t*)&Ph[r0 * PP + k + 8 + tig * 2];
                ph_[mi][3] = *(const uint32_t*)&Ph[(r0 + 8) * PP + k + 8 + tig * 2];
                pl_[mi][0] = *(const uint32_t*)&Pl[r0 * PP + k + tig * 2];
                pl_[mi][1] = *(const uint32_t*)&Pl[(r0 + 8) * PP + k + tig * 2];
                pl_[mi][2] = *(const uint32_t*)&Pl[r0 * PP + k + 8 + tig * 2];
                pl_[mi][3] = *(const uint32_t*)&Pl[(r0 + 8) * PP + k + 8 + tig * 2];
            }
#pragma unroll
            for (int ni = 0; ni < 2; ni++) {
                const int n0 = wn2 + ni * 8 + g;
                const uint32_t vh0 = *(const uint32_t*)&Vth[n0 * PP + k + tig * 2];
                const uint32_t vh1 = *(const uint32_t*)&Vth[n0 * PP + k + 8 + tig * 2];
                const uint32_t vl0 = *(const uint32_t*)&Vtl[n0 * PP + k + tig * 2];
                const uint32_t vl1 = *(const uint32_t*)&Vtl[n0 * PP + k + 8 + tig * 2];
#pragma unroll
                for (int mi = 0; mi < 2; mi++) {
                    mma16816(oacc[mi][ni], ph_[mi], vh0, vh1);
                    mma16816(oacc[mi][ni], ph_[mi], vl0, vl1);
                    mma16816(oacc[mi][ni], pl_[mi], vh0, vh1);
                }
            }
        }

        // store O chunk
#pragma unroll
        for (int mi = 0; mi < 2; mi++) {
#pragma unroll
            for (int ni = 0; ni < 2; ni++) {
                const int m0 = wm + mi * 16 + g;
                const int col = d0 + wn2 + ni * 8 + tig * 2;
                const size_t row = (size_t)b * T_SZ + i0 + m0;
                float2 v0 = {oacc[mi][ni][0], oacc[mi][ni][1]};
                float2 v1 = {oacc[mi][ni][2], oacc[mi][ni][3]};
                *(float2*)&out[row * DIM + col]       = v0;
                *(float2*)&out[(row + 8) * DIM + col] = v1;
            }
        }
    }
}

// ---------------- launch -----------------------------------------------------
extern "C" void kernel_launch(void* const* d_in, const int* in_sizes, int n_in,
                              void* d_out, int out_size)
{
    const float* x    = (const float*)d_in[0];
    const float* Wqkv = (const float*)d_in[1];
    const float* bqkv = (const float*)d_in[2];
    float* out = (float*)d_out;

    cudaFuncSetAttribute(attn_mma,
                         cudaFuncAttributeMaxDynamicSharedMemorySize, AT_SMEM);

    __nv_bfloat16 *ah, *al, *wh, *wl;
    cudaGetSymbolAddress((void**)&ah, g_Ah);
    cudaGetSymbolAddress((void**)&al, g_Al);
    cudaGetSymbolAddress((void**)&wh, g_Wh);
    cudaGetSymbolAddress((void**)&wl, g_Wl);

    {
        int n4 = (M_TOT * DIM) / 4;
        cvt_split<<<(n4 + 255) / 256, 256>>>(x, ah, al, n4);
    }
    {
        int n4 = (E3 * DIM) / 4;
        cvt_split<<<(n4 + 255) / 256, 256>>>(Wqkv, wh, wl, n4);
    }

    dim3 ggrid(E3 / GBN, M_TOT / GBM);       // (12, 128)
    qkv_mma<<<ggrid, 256>>>(bqkv);

    dim3 agrid(T_SZ / QT, B_SZ);             // (64, 4)
    attn_mma<<<agrid, 256, AT_SMEM>>>(out);
}